// round 6
// baseline (speedup 1.0000x reference)
#include <cuda_runtime.h>
#include <math.h>

#define NA 4096
#define NP 8192
#define NT 4096
#define NC 2048
typedef unsigned long long ull;

__device__ float g_ha[NA*128];
__device__ float g_hp[NP*128];
__device__ float g_ht[NT*128];
__device__ float g_hc[NC*128];
__device__ float g_xt[NA*128];
__device__ float g_an[NA*128];
__device__ float g_snp[NP*128];
__device__ float g_snt[NT*128];
__device__ float g_snc[NC*128];
__device__ float g_gp[NP*128];
__device__ float g_gt[NT*128];
__device__ float g_gc[NC*128];
__device__ float g_alsp[NP];
__device__ float g_alst[NT];
__device__ float g_alsc[NC];
__device__ float g_ald[3*NA];
__device__ float g_wdv[3*128];
__device__ unsigned g_mxsEnc[3];
__device__ float g_acc[3*NA*128];
__device__ float g_den[3*NA];
__device__ float g_ssum[4];
__device__ float g_alpha[4];
__device__ float g_agg1[NA*128];
__device__ float g_deg[NA];
__device__ float g_h1[NA*256];
__device__ float g_q[NA*64];
__device__ float g_aggq[NA*64];

__device__ __forceinline__ void fma2(ull& d, ull a, ull b) {
    asm("fma.rn.f32x2 %0, %1, %2, %0;" : "+l"(d) : "l"(a), "l"(b));
}
__device__ __forceinline__ ull pack2(float x, float y) {
    ull r; asm("mov.b64 %0, {%1, %2};" : "=l"(r) : "f"(x), "f"(y)); return r;
}
__device__ __forceinline__ float2 unpack2(ull v) {
    float2 r; asm("mov.b64 {%0, %1}, %2;" : "=f"(r.x), "=f"(r.y) : "l"(v)); return r;
}
__device__ __forceinline__ unsigned enc_f(float f) {
    unsigned b = __float_as_uint(f);
    return (b & 0x80000000u) ? ~b : (b | 0x80000000u);
}
__device__ __forceinline__ float dec_f(unsigned u) {
    unsigned b = (u & 0x80000000u) ? (u ^ 0x80000000u) : ~u;
    return __uint_as_float(b);
}

// ---------- fused zero init ----------
__global__ void zero_all(float* __restrict__ acc, float* __restrict__ agg1,
                         float* __restrict__ aggq, float* __restrict__ den,
                         float* __restrict__ deg, float* __restrict__ ssum,
                         unsigned* __restrict__ mxsEnc) {
    int i = blockIdx.x * 256 + threadIdx.x;
    if (i < 1572864) { acc[i] = 0.f; return; }
    i -= 1572864; if (i < 524288) { agg1[i] = 0.f; return; }
    i -= 524288;  if (i < 262144) { aggq[i] = 0.f; return; }
    i -= 262144;  if (i < 12288)  { den[i] = 0.f; return; }
    i -= 12288;   if (i < 4096)   { deg[i] = 0.f; return; }
    i -= 4096;    if (i < 4)      { ssum[i] = 0.f; return; }
    i -= 4;       if (i < 3)      mxsEnc[i] = enc_f(-3.0e38f);
}

// ---------- wdv[i][k] = sum_c gWd[i][k][c]*gad[i][c] ----------
__global__ void wvec_kernel(const float* __restrict__ W3, const float* __restrict__ a3,
                            float* __restrict__ out3) {
    int i = blockIdx.x, k = threadIdx.x;
    __shared__ float sa[128];
    sa[k] = a3[i * 128 + k];
    __syncthreads();
    const float* W = W3 + (size_t)i * 16384 + (size_t)k * 128;
    float s = 0.f;
    #pragma unroll 8
    for (int c = 0; c < 128; c++) s += W[c] * sa[c];
    out3[i * 128 + k] = s;
}

// ---------- batched linear ----------
struct LJob {
    const float *A, *W, *A2, *W2, *bias, *addD, *degp;
    float* C;
    int M, K, K2, N, relu, colBlks, blkStart;
};
struct LJobs { LJob j[5]; int n; };

__global__ __launch_bounds__(256) void lin_batch(LJobs P) {
    int bid = blockIdx.x;
    int sel = 0;
    #pragma unroll
    for (int i = 1; i < 5; i++)
        if (i < P.n && bid >= P.j[i].blkStart) sel = i;
    LJob J = P.j[sel];
    int rel = bid - J.blkStart;
    int rb = (rel / J.colBlks) * 64, cb = (rel % J.colBlks) * 128;

    __shared__ float As[16][64];
    __shared__ float Ws[16][128];
    int t = threadIdx.x, cg = t & 31, rg = t >> 5;
    float acc[8][4];
    #pragma unroll
    for (int i = 0; i < 8; i++)
        #pragma unroll
        for (int j = 0; j < 4; j++) acc[i][j] = 0.f;

    #pragma unroll 1
    for (int ph = 0; ph < 2; ph++) {
        const float* A = ph ? J.A2 : J.A;
        const float* W = ph ? J.W2 : J.W;
        int K = ph ? J.K2 : J.K;
        if (!A) break;
        for (int k0 = 0; k0 < K; k0 += 16) {
            for (int i = t; i < 1024; i += 256) {
                int r = i >> 4, kk = i & 15, kg = k0 + kk;
                As[kk][r] = (kg < K) ? A[(size_t)(rb + r) * K + kg] : 0.f;
            }
            for (int i = t; i < 2048; i += 256) {
                int kk = i >> 7, c = i & 127, kg = k0 + kk;
                Ws[kk][c] = (kg < K && (cb + c) < J.N) ? W[(size_t)kg * J.N + cb + c] : 0.f;
            }
            __syncthreads();
            #pragma unroll
            for (int kk = 0; kk < 16; kk++) {
                float4 w4 = *(float4*)&Ws[kk][cg * 4];
                #pragma unroll
                for (int i = 0; i < 8; i++) {
                    float a = As[kk][rg * 8 + i];
                    acc[i][0] += a * w4.x; acc[i][1] += a * w4.y;
                    acc[i][2] += a * w4.z; acc[i][3] += a * w4.w;
                }
            }
            __syncthreads();
        }
    }
    #pragma unroll
    for (int i = 0; i < 8; i++) {
        int row = rb + rg * 8 + i;
        float dscale = J.degp ? 1.f / fmaxf(J.degp[row], 1.f) : 1.f;
        #pragma unroll
        for (int j = 0; j < 4; j++) {
            int col = cb + cg * 4 + j;
            if (col < J.N) {
                float v = acc[i][j];
                if (J.bias) v += J.bias[col];
                if (J.addD) v += J.addD[(size_t)row * J.N + col] * dscale;
                if (J.relu) v = fmaxf(v, 0.f);
                J.C[(size_t)row * J.N + col] = v;
            }
        }
    }
}

// ---------- fused prep: rownorms + matvecs(+max) ----------
__global__ void prep_all(
    const float* __restrict__ ha, const float* __restrict__ hp,
    const float* __restrict__ ht, const float* __restrict__ hc,
    float* __restrict__ an, float* __restrict__ snp,
    float* __restrict__ snt, float* __restrict__ snc,
    const float* __restrict__ gp, const float* __restrict__ gt, const float* __restrict__ gc,
    const float* __restrict__ wdv, const float* __restrict__ gas,
    float* __restrict__ ald, float* __restrict__ alsp, float* __restrict__ alst,
    float* __restrict__ alsc, unsigned* __restrict__ mxsEnc)
{
    int m = blockIdx.x, t = threadIdx.x;
    __shared__ float ws[4];
    if (m < 18432) {
        const float* X; float* Y; int r;
        if (m < 4096)       { X = ha; Y = an;  r = m; }
        else if (m < 12288) { X = hp; Y = snp; r = m - 4096; }
        else if (m < 16384) { X = ht; Y = snt; r = m - 12288; }
        else                { X = hc; Y = snc; r = m - 16384; }
        float v = X[(size_t)r * 128 + t];
        float s = v * v;
        #pragma unroll
        for (int o = 16; o; o >>= 1) s += __shfl_xor_sync(0xffffffffu, s, o);
        if ((t & 31) == 0) ws[t >> 5] = s;
        __syncthreads();
        float tot = ws[0] + ws[1] + ws[2] + ws[3];
        Y[(size_t)r * 128 + t] = v / fmaxf(sqrtf(tot), 1e-12f);
    } else {
        int m2 = m - 18432;
        const float* X; const float* vec; float* y; int r; int mxi = -1;
        if (m2 < 12288) {
            int tpe = m2 >> 12;
            X = ha; vec = wdv + tpe * 128; y = ald + tpe * NA; r = m2 & 4095;
        } else {
            int m3 = m2 - 12288;
            if (m3 < 8192)       { X = gp; vec = gas;       y = alsp; r = m3;         mxi = 0; }
            else if (m3 < 12288) { X = gt; vec = gas + 128; y = alst; r = m3 - 8192;  mxi = 1; }
            else                 { X = gc; vec = gas + 256; y = alsc; r = m3 - 12288; mxi = 2; }
        }
        float s = X[(size_t)r * 128 + t] * vec[t];
        #pragma unroll
        for (int o = 16; o; o >>= 1) s += __shfl_xor_sync(0xffffffffu, s, o);
        if ((t & 31) == 0) ws[t >> 5] = s;
        __syncthreads();
        if (t == 0) {
            float tot = ws[0] + ws[1] + ws[2] + ws[3];
            y[r] = tot;
            if (mxi >= 0) atomicMax(&mxsEnc[mxi], enc_f(tot));
        }
    }
}

// ---------- hetero flush ----------
__device__ __forceinline__ void hetero_flush(
    float* __restrict__ acc, float* __restrict__ deng, const float* __restrict__ sDEN,
    ull (&num2)[4][4], int curType, int r0g, int rg, int cg)
{
    float* accT = acc + (size_t)curType * NA * 128;
    #pragma unroll
    for (int i = 0; i < 4; i++) {
        size_t base = (size_t)(r0g + rg * 4 + i) * 128 + cg * 8;
        #pragma unroll
        for (int p = 0; p < 4; p++) {
            float2 v = unpack2(num2[i][p]);
            atomicAdd(&accT[base + p * 2],     v.x);
            atomicAdd(&accT[base + p * 2 + 1], v.y);
        }
    }
    if (cg == 0) {
        #pragma unroll
        for (int i = 0; i < 4; i++)
            atomicAdd(&deng[curType * NA + r0g + rg * 4 + i], sDEN[rg * 4 + i]);
    }
}

// ---------- persistent fused hetero GAT, big register tiles ----------
// block: 64 authors x 128-src chunks, 256 threads, 1 CTA/SM, grid 152.
// phase1 thread tile 4x8 (packed-k), phase2 thread tile 4x8 (packed dims).
#define HET_GRID 152
#define SM_AN   0
#define SM_B2   32768
#define SM_HS   99328
#define SM_W    164864
#define SM_ALD  198656
#define SM_DEN  198912
#define SM_ALS  199168
#define SM_TOT  199680

__global__ __launch_bounds__(256, 1) void hetero_kernel(
    const float* __restrict__ an, const float* __restrict__ ald3,
    const unsigned* __restrict__ mxsEnc,
    const float* __restrict__ snp, const float* __restrict__ gp, const float* __restrict__ alsp,
    const float* __restrict__ snt, const float* __restrict__ gt, const float* __restrict__ alst,
    const float* __restrict__ snc, const float* __restrict__ gc, const float* __restrict__ alsc,
    float* __restrict__ acc, float* __restrict__ deng)
{
    extern __shared__ char smraw[];
    float* sAN  = (float*)(smraw + SM_AN);    // 64 x 128 f
    ull*   sB2  = (ull*)(smraw + SM_B2);      // 64 kpairs x 130 src (ull)
    float* sHS  = (float*)(smraw + SM_HS);    // 128 src x 128 dim f
    float* sW   = (float*)(smraw + SM_W);     // 64 au x 132 src f
    float* sALD = (float*)(smraw + SM_ALD);
    float* sDEN = (float*)(smraw + SM_DEN);
    float* sALS = (float*)(smraw + SM_ALS);   // 128
    ull* sANu = (ull*)sAN;
    ull* sHSu = (ull*)sHS;

    const int TOT = 7168;  // 64 aub * (64 + 32 + 16)
    int bid = blockIdx.x;
    int cs = (int)(((long long)bid * TOT) / HET_GRID);
    int ce = (int)(((long long)(bid + 1) * TOT) / HET_GRID);
    int t = threadIdx.x, cg = t & 15, rg = t >> 4;

    int curType = -1, curAb = -1, r0g = 0;
    float mx = 0.f;
    const float *sn = snp, *hs = gp, *als = alsp;
    ull num2[4][4];

    for (int c = cs; c < ce; c++) {
        int type, ab, ch;
        if (c < 4096)      { type = 0; ab = c >> 6; ch = c & 63; }
        else if (c < 6144) { int c2 = c - 4096; type = 1; ab = c2 >> 5; ch = c2 & 31; }
        else               { int c2 = c - 6144; type = 2; ab = c2 >> 4; ch = c2 & 15; }
        int j0 = ch << 7;

        if (type != curType || ab != curAb) {
            if (curType >= 0) {
                hetero_flush(acc, deng, sDEN, num2, curType, r0g, rg, cg);
                __syncthreads();
            }
            curType = type; curAb = ab; r0g = ab << 6;
            if (type == 0)      { sn = snp; hs = gp; als = alsp; }
            else if (type == 1) { sn = snt; hs = gt; als = alst; }
            else                { sn = snc; hs = gc; als = alsc; }
            mx = dec_f(mxsEnc[type]);
            for (int i = t; i < 2048; i += 256) {
                int r = i >> 5, q = i & 31;
                *(float4*)&sAN[r * 128 + q * 4] =
                    *(const float4*)&an[(size_t)(r0g + r) * 128 + q * 4];
            }
            if (t < 64) { sALD[t] = ald3[type * NA + r0g + t]; sDEN[t] = 0.f; }
            #pragma unroll
            for (int i = 0; i < 4; i++)
                #pragma unroll
                for (int p = 0; p < 4; p++) num2[i][p] = 0ull;
            __syncthreads();
        }

        // load SN chunk (kpair-major, src-fast -> conflict-free STS.64)
        for (int i = t; i < 4096; i += 256) {
            int j = i & 127, q = i >> 7;   // q = float4 idx 0..31
            float4 v = *(const float4*)&sn[(size_t)(j0 + j) * 128 + q * 4];
            sB2[(2 * q) * 130 + j]     = pack2(v.x, v.y);
            sB2[(2 * q + 1) * 130 + j] = pack2(v.z, v.w);
        }
        // load HS chunk (dim-fast -> conflict-free STS.128)
        for (int i = t; i < 4096; i += 256) {
            int q = i & 31, j = i >> 5;
            *(float4*)&sHS[j * 128 + q * 4] =
                *(const float4*)&hs[(size_t)(j0 + j) * 128 + q * 4];
        }
        if (t < 128) sALS[t] = als[j0 + t];
        __syncthreads();

        // phase 1: S[4 rows][8 cols], packed over k
        ull S2[4][8];
        #pragma unroll
        for (int i = 0; i < 4; i++)
            #pragma unroll
            for (int j = 0; j < 8; j++) S2[i][j] = 0ull;
        #pragma unroll 2
        for (int qq = 0; qq < 32; qq++) {
            ulonglong2 a[4];
            #pragma unroll
            for (int i = 0; i < 4; i++)
                a[i] = *(ulonglong2*)&sANu[(rg * 4 + i) * 64 + 2 * qq];
            const ull* B0 = &sB2[(2 * qq) * 130 + cg * 8];
            const ull* B1 = &sB2[(2 * qq + 1) * 130 + cg * 8];
            #pragma unroll
            for (int jb = 0; jb < 4; jb++) {
                ulonglong2 b0 = *(ulonglong2*)&B0[jb * 2];
                ulonglong2 b1 = *(ulonglong2*)&B1[jb * 2];
                #pragma unroll
                for (int i = 0; i < 4; i++) {
                    fma2(S2[i][jb * 2],     a[i].x, b0.x);
                    fma2(S2[i][jb * 2 + 1], a[i].x, b0.y);
                    fma2(S2[i][jb * 2],     a[i].y, b1.x);
                    fma2(S2[i][jb * 2 + 1], a[i].y, b1.y);
                }
            }
        }

        // phase 1.5: attention weights + row denominators
        float rsum[4];
        #pragma unroll
        for (int i = 0; i < 4; i++) {
            float aldr = sALD[rg * 4 + i];
            float tm = aldr + mx;
            float mrow = tm >= 0.f ? tm : 0.2f * tm;
            rsum[i] = 0.f;
            #pragma unroll
            for (int jj = 0; jj < 8; jj++) {
                float2 sp = unpack2(S2[i][jj]);
                float sval = sp.x + sp.y;
                float w = 0.f;
                int jgl = j0 + cg * 8 + jj;
                if (sval > 0.1f && (r0g + rg * 4 + i) != jgl) {
                    float e0 = aldr + sALS[cg * 8 + jj];
                    float e = e0 >= 0.f ? e0 : 0.2f * e0;
                    w = __expf(e - mrow);
                }
                sW[(rg * 4 + i) * 132 + cg * 8 + jj] = w;
                rsum[i] += w;
            }
        }
        #pragma unroll
        for (int o = 1; o < 16; o <<= 1)
            #pragma unroll
            for (int i = 0; i < 4; i++)
                rsum[i] += __shfl_xor_sync(0xffffffffu, rsum[i], o);
        if (cg == 0)
            #pragma unroll
            for (int i = 0; i < 4; i++) sDEN[rg * 4 + i] += rsum[i];
        __syncthreads();

        // phase 2: num[64 au][128 dim] += W[64 au][128 src] @ HS[128 src][128 dim]
        #pragma unroll 2
        for (int j = 0; j < 128; j++) {
            ulonglong2 h0 = *(ulonglong2*)&sHSu[j * 64 + cg * 4];
            ulonglong2 h1 = *(ulonglong2*)&sHSu[j * 64 + cg * 4 + 2];
            #pragma unroll
            for (int i = 0; i < 4; i++) {
                float w = sW[(rg * 4 + i) * 132 + j];
                ull wp = pack2(w, w);
                fma2(num2[i][0], wp, h0.x); fma2(num2[i][1], wp, h0.y);
                fma2(num2[i][2], wp, h1.x); fma2(num2[i][3], wp, h1.y);
            }
        }
        __syncthreads();
    }
    if (curType >= 0)
        hetero_flush(acc, deng, sDEN, num2, curType, r0g, rg, cg);
}

__global__ void finalize_kernel(float* __restrict__ acc, const float* __restrict__ den,
                                const float* __restrict__ gb) {
    int idx = blockIdx.x * blockDim.x + threadIdx.x;
    if (idx >= 3 * NA * 128) return;
    int c = idx & 127, dr = idx >> 7, type = idx >> 19;
    float d = den[dr], b = gb[type * 128 + c];
    acc[idx] = (d > 0.f) ? acc[idx] / d + b : b;
}

__global__ void attscore_kernel(const float* __restrict__ heter, const float* __restrict__ xt,
                                const float* __restrict__ Watt, const float* __restrict__ atts,
                                float* __restrict__ ssum) {
    int set = blockIdx.y;
    const float* X = (set < 3) ? heter + (size_t)set * NA * 128 : xt;
    int rb = blockIdx.x * 4, t = threadIdx.x, c = t & 63;
    __shared__ float xs[4][128];
    for (int i = t; i < 512; i += 256)
        xs[i >> 7][i & 127] = X[(size_t)(rb + (i >> 7)) * 128 + (i & 127)];
    __syncthreads();
    const float* xr = xs[t >> 6];
    float dot = 0.f;
    #pragma unroll 8
    for (int k = 0; k < 128; k++) dot += xr[k] * Watt[k * 64 + c];
    float val = (1.f / (1.f + __expf(-dot))) * atts[set * 64 + c];
    #pragma unroll
    for (int o = 16; o; o >>= 1) val += __shfl_xor_sync(0xffffffffu, val, o);
    __shared__ float ps[8];
    if ((t & 31) == 0) ps[t >> 5] = val;
    __syncthreads();
    if (t == 0) {
        float s = 0.f;
        #pragma unroll
        for (int i = 0; i < 8; i++) s += ps[i];
        atomicAdd(&ssum[set], s);
    }
}

__global__ void alpha_kernel(const float* __restrict__ ssum, float* __restrict__ alpha) {
    if (threadIdx.x == 0) {
        float s[4], m = -3e38f;
        for (int i = 0; i < 4; i++) { s[i] = ssum[i] / (float)NA; m = fmaxf(m, s[i]); }
        float e[4], tot = 0.f;
        for (int i = 0; i < 4; i++) { e[i] = expf(s[i] - m); tot += e[i]; }
        for (int i = 0; i < 4; i++) alpha[i] = e[i] / tot;
    }
}

__global__ void xatt_kernel(const float* __restrict__ heter, const float* __restrict__ xt,
                            const float* __restrict__ alpha, float* __restrict__ out) {
    int idx = blockIdx.x * blockDim.x + threadIdx.x;
    if (idx >= NA * 128) return;
    out[idx] = alpha[0] * heter[idx] + alpha[1] * heter[NA * 128 + idx] +
               alpha[2] * heter[2 * NA * 128 + idx] + alpha[3] * xt[idx];
}

__global__ void deg_kernel(const int* __restrict__ dst, float* __restrict__ deg, int E) {
    int e = blockIdx.x * blockDim.x + threadIdx.x;
    if (e < E) atomicAdd(&deg[dst[e]], 1.0f);
}

__global__ void scatter_kernel(const float* __restrict__ X, const int* __restrict__ src,
                               const int* __restrict__ dst, float* __restrict__ AGG,
                               int E, int C) {
    int idx = blockIdx.x * blockDim.x + threadIdx.x;
    int per = C >> 2;
    if (idx >= E * per) return;
    int e = idx / per, q = idx - e * per;
    int s = src[e], d = dst[e];
    float4 v = *(const float4*)&X[(size_t)s * C + q * 4];
    float* o = &AGG[(size_t)d * C + q * 4];
    atomicAdd(o + 0, v.x); atomicAdd(o + 1, v.y);
    atomicAdd(o + 2, v.z); atomicAdd(o + 3, v.w);
}

__global__ void rowdiv_kernel(float* __restrict__ AGG, const float* __restrict__ deg,
                              int n, int C) {
    int idx = blockIdx.x * blockDim.x + threadIdx.x;
    if (idx >= n) return;
    AGG[idx] = AGG[idx] / fmaxf(deg[idx / C], 1.0f);
}

extern "C" void kernel_launch(void* const* d_in, const int* in_sizes, int n_in,
                              void* d_out, int out_size) {
    const float* x_ma = (const float*)d_in[0];
    const float* x_mp = (const float*)d_in[1];
    const float* x_mt = (const float*)d_in[2];
    const float* x_mc = (const float*)d_in[3];
    const float* x_ia = (const float*)d_in[4];
    const int*   edge = (const int*)d_in[5];
    const float* Wla  = (const float*)d_in[6];  const float* bla  = (const float*)d_in[7];
    const float* Wlp  = (const float*)d_in[8];  const float* blp  = (const float*)d_in[9];
    const float* Wlt  = (const float*)d_in[10]; const float* blt  = (const float*)d_in[11];
    const float* Wlc  = (const float*)d_in[12]; const float* blc  = (const float*)d_in[13];
    const float* Wltg = (const float*)d_in[14]; const float* bltg = (const float*)d_in[15];
    const float* gWs  = (const float*)d_in[16];
    const float* gWd  = (const float*)d_in[17];
    const float* gas  = (const float*)d_in[18];
    const float* gad  = (const float*)d_in[19];
    const float* gb   = (const float*)d_in[20];
    const float* Watt = (const float*)d_in[21];
    const float* atts = (const float*)d_in[22];
    const float* W1l  = (const float*)d_in[23]; const float* b1 = (const float*)d_in[24];
    const float* W1r  = (const float*)d_in[25];
    const float* W2l  = (const float*)d_in[26]; const float* b2 = (const float*)d_in[27];
    const float* W2r  = (const float*)d_in[28];

    int E = in_sizes[5] / 2;
    int Ka = in_sizes[0] / NA, Kp = in_sizes[1] / NP, Kt = in_sizes[2] / NT;
    int Kc = in_sizes[3] / NC, Kg = in_sizes[4] / NA;

    float* out_x   = (float*)d_out;
    float* out_att = (float*)d_out + (size_t)NA * 64;

    float *ha,*hp,*ht,*hc,*xt,*an,*snp,*snt,*snc,*gp,*gt,*gc;
    float *alsp,*alst,*alsc,*ald,*wdv,*acc,*den,*ssum,*alpha,*agg1,*deg,*h1,*q,*aggq;
    unsigned* mxsEnc;
    cudaGetSymbolAddress((void**)&ha,g_ha);   cudaGetSymbolAddress((void**)&hp,g_hp);
    cudaGetSymbolAddress((void**)&ht,g_ht);   cudaGetSymbolAddress((void**)&hc,g_hc);
    cudaGetSymbolAddress((void**)&xt,g_xt);   cudaGetSymbolAddress((void**)&an,g_an);
    cudaGetSymbolAddress((void**)&snp,g_snp); cudaGetSymbolAddress((void**)&snt,g_snt);
    cudaGetSymbolAddress((void**)&snc,g_snc); cudaGetSymbolAddress((void**)&gp,g_gp);
    cudaGetSymbolAddress((void**)&gt,g_gt);   cudaGetSymbolAddress((void**)&gc,g_gc);
    cudaGetSymbolAddress((void**)&alsp,g_alsp); cudaGetSymbolAddress((void**)&alst,g_alst);
    cudaGetSymbolAddress((void**)&alsc,g_alsc); cudaGetSymbolAddress((void**)&ald,g_ald);
    cudaGetSymbolAddress((void**)&wdv,g_wdv);   cudaGetSymbolAddress((void**)&mxsEnc,g_mxsEnc);
    cudaGetSymbolAddress((void**)&acc,g_acc);   cudaGetSymbolAddress((void**)&den,g_den);
    cudaGetSymbolAddress((void**)&ssum,g_ssum); cudaGetSymbolAddress((void**)&alpha,g_alpha);
    cudaGetSymbolAddress((void**)&agg1,g_agg1); cudaGetSymbolAddress((void**)&deg,g_deg);
    cudaGetSymbolAddress((void**)&h1,g_h1);     cudaGetSymbolAddress((void**)&q,g_q);
    cudaGetSymbolAddress((void**)&aggq,g_aggq);

    auto mkjob = [](const float*A,const float*W,const float*A2,const float*W2,
                    const float*bias,const float*addD,const float*degp,float*C,
                    int M,int K,int K2,int N,int relu,int colBlks,int blkStart){
        LJob J; J.A=A;J.W=W;J.A2=A2;J.W2=W2;J.bias=bias;J.addD=addD;J.degp=degp;J.C=C;
        J.M=M;J.K=K;J.K2=K2;J.N=N;J.relu=relu;J.colBlks=colBlks;J.blkStart=blkStart;
        return J;
    };

    wvec_kernel<<<3,128>>>(gWd, gad, wdv);
    zero_all<<<9281,256>>>(acc, agg1, aggq, den, deg, ssum, mxsEnc);
    {
        LJobs B; B.n = 5;
        B.j[0] = mkjob(x_ma, Wla,  0,0, bla,  0,0, ha, NA, Ka, 0, 128, 0, 1, 0);
        B.j[1] = mkjob(x_mp, Wlp,  0,0, blp,  0,0, hp, NP, Kp, 0, 128, 0, 1, 64);
        B.j[2] = mkjob(x_mt, Wlt,  0,0, blt,  0,0, ht, NT, Kt, 0, 128, 0, 1, 192);
        B.j[3] = mkjob(x_mc, Wlc,  0,0, blc,  0,0, hc, NC, Kc, 0, 128, 0, 1, 256);
        B.j[4] = mkjob(x_ia, Wltg, 0,0, bltg, 0,0, xt, NA, Kg, 0, 128, 0, 1, 288);
        lin_batch<<<352,256>>>(B);
    }
    {
        LJobs B; B.n = 3;
        B.j[0] = mkjob(hp, gWs + 0*16384, 0,0, 0,0,0, gp, NP, 128, 0, 128, 0, 1, 0);
        B.j[1] = mkjob(ht, gWs + 1*16384, 0,0, 0,0,0, gt, NT, 128, 0, 128, 0, 1, 128);
        B.j[2] = mkjob(hc, gWs + 2*16384, 0,0, 0,0,0, gc, NC, 128, 0, 128, 0, 1, 192);
        lin_batch<<<224,256>>>(B);
    }
    prep_all<<<45056,128>>>(ha, hp, ht, hc, an, snp, snt, snc,
                            gp, gt, gc, wdv, gas, ald, alsp, alst, alsc, mxsEnc);
    cudaFuncSetAttribute(hetero_kernel, cudaFuncAttributeMaxDynamicSharedMemorySize, SM_TOT);
    hetero_kernel<<<HET_GRID,256,SM_TOT>>>(an, ald, mxsEnc, snp, gp, alsp,
                                           snt, gt, alst, snc, gc, alsc, acc, den);
    finalize_kernel<<<(3*NA*128)/256,256>>>(acc, den, gb);
    attscore_kernel<<<dim3(NA/4,4),256>>>(acc, xt, Watt, atts, ssum);
    alpha_kernel<<<1,32>>>(ssum, alpha);
    xatt_kernel<<<(NA*128)/256,256>>>(acc, xt, alpha, out_att);
    deg_kernel<<<(E+255)/256,256>>>(edge + E, deg, E);
    scatter_kernel<<<(E*32)/256,256>>>(ha, edge, edge + E, agg1, E, 128);
    rowdiv_kernel<<<(NA*128)/256,256>>>(agg1, deg, NA*128, 128);
    {
        LJobs B; B.n = 1;
        B.j[0] = mkjob(agg1, W1l, ha, W1r, b1, 0,0, h1, NA, 128, 128, 256, 1, 2, 0);
        lin_batch<<<128,256>>>(B);
    }
    {
        LJobs B; B.n = 1;
        B.j[0] = mkjob(h1, W2l, 0,0, 0,0,0, q, NA, 256, 0, 64, 0, 1, 0);
        lin_batch<<<64,256>>>(B);
    }
    scatter_kernel<<<(E*16)/256,256>>>(q, edge, edge + E, aggq, E, 64);
    {
        LJobs B; B.n = 1;
        B.j[0] = mkjob(h1, W2r, 0,0, b2, aggq, deg, out_x, NA, 256, 0, 64, 0, 1, 0);
        lin_batch<<<64,256>>>(B);
    }
}

// round 7
// speedup vs baseline: 1.4564x; 1.4564x over previous
#include <cuda_runtime.h>
#include <math.h>

#define NA 4096
#define NP 8192
#define NT 4096
#define NC 2048
typedef unsigned long long ull;

__device__ float g_ha[NA*128];
__device__ float g_hp[NP*128];
__device__ float g_ht[NT*128];
__device__ float g_hc[NC*128];
__device__ float g_xt[NA*128];
__device__ float g_an[NA*128];
__device__ float g_snp[NP*128];
__device__ float g_snt[NT*128];
__device__ float g_snc[NC*128];
__device__ float g_gp[NP*128];
__device__ float g_gt[NT*128];
__device__ float g_gc[NC*128];
__device__ float g_alsp[NP];
__device__ float g_alst[NT];
__device__ float g_alsc[NC];
__device__ float g_ald[3*NA];
__device__ float g_wdv[3*128];
__device__ unsigned g_mxsEnc[3];
__device__ float g_acc[3*NA*128];
__device__ float g_den[3*NA];
__device__ float g_ssum[4];
__device__ float g_alpha[4];
__device__ float g_agg1[NA*128];
__device__ float g_deg[NA];
__device__ float g_h1[NA*256];
__device__ float g_q[NA*64];
__device__ float g_aggq[NA*64];

__device__ __forceinline__ void fma2(ull& d, ull a, ull b) {
    asm("fma.rn.f32x2 %0, %1, %2, %0;" : "+l"(d) : "l"(a), "l"(b));
}
__device__ __forceinline__ ull pack2(float x, float y) {
    ull r; asm("mov.b64 %0, {%1, %2};" : "=l"(r) : "f"(x), "f"(y)); return r;
}
__device__ __forceinline__ float2 unpack2(ull v) {
    float2 r; asm("mov.b64 {%0, %1}, %2;" : "=f"(r.x), "=f"(r.y) : "l"(v)); return r;
}
__device__ __forceinline__ unsigned enc_f(float f) {
    unsigned b = __float_as_uint(f);
    return (b & 0x80000000u) ? ~b : (b | 0x80000000u);
}
__device__ __forceinline__ float dec_f(unsigned u) {
    unsigned b = (u & 0x80000000u) ? (u ^ 0x80000000u) : ~u;
    return __uint_as_float(b);
}

// ---------- fused zero init ----------
__global__ void zero_all(float* __restrict__ acc, float* __restrict__ agg1,
                         float* __restrict__ aggq, float* __restrict__ den,
                         float* __restrict__ deg, float* __restrict__ ssum,
                         unsigned* __restrict__ mxsEnc) {
    int i = blockIdx.x * 256 + threadIdx.x;
    if (i < 1572864) { acc[i] = 0.f; return; }
    i -= 1572864; if (i < 524288) { agg1[i] = 0.f; return; }
    i -= 524288;  if (i < 262144) { aggq[i] = 0.f; return; }
    i -= 262144;  if (i < 12288)  { den[i] = 0.f; return; }
    i -= 12288;   if (i < 4096)   { deg[i] = 0.f; return; }
    i -= 4096;    if (i < 4)      { ssum[i] = 0.f; return; }
    i -= 4;       if (i < 3)      mxsEnc[i] = enc_f(-3.0e38f);
}

// ---------- wdv[i][k] = sum_c gWd[i][k][c]*gad[i][c] ----------
__global__ void wvec_kernel(const float* __restrict__ W3, const float* __restrict__ a3,
                            float* __restrict__ out3) {
    int i = blockIdx.x, k = threadIdx.x;
    __shared__ float sa[128];
    sa[k] = a3[i * 128 + k];
    __syncthreads();
    const float* W = W3 + (size_t)i * 16384 + (size_t)k * 128;
    float s = 0.f;
    #pragma unroll 8
    for (int c = 0; c < 128; c++) s += W[c] * sa[c];
    out3[i * 128 + k] = s;
}

// ---------- batched linear ----------
struct LJob {
    const float *A, *W, *A2, *W2, *bias, *addD, *degp;
    float* C;
    int M, K, K2, N, relu, colBlks, blkStart;
};
struct LJobs { LJob j[5]; int n; };

__global__ __launch_bounds__(256) void lin_batch(LJobs P) {
    int bid = blockIdx.x;
    int sel = 0;
    #pragma unroll
    for (int i = 1; i < 5; i++)
        if (i < P.n && bid >= P.j[i].blkStart) sel = i;
    LJob J = P.j[sel];
    int rel = bid - J.blkStart;
    int rb = (rel / J.colBlks) * 64, cb = (rel % J.colBlks) * 128;

    __shared__ float As[16][64];
    __shared__ float Ws[16][128];
    int t = threadIdx.x, cg = t & 31, rg = t >> 5;
    float acc[8][4];
    #pragma unroll
    for (int i = 0; i < 8; i++)
        #pragma unroll
        for (int j = 0; j < 4; j++) acc[i][j] = 0.f;

    #pragma unroll 1
    for (int ph = 0; ph < 2; ph++) {
        const float* A = ph ? J.A2 : J.A;
        const float* W = ph ? J.W2 : J.W;
        int K = ph ? J.K2 : J.K;
        if (!A) break;
        for (int k0 = 0; k0 < K; k0 += 16) {
            for (int i = t; i < 1024; i += 256) {
                int r = i >> 4, kk = i & 15, kg = k0 + kk;
                As[kk][r] = (kg < K) ? A[(size_t)(rb + r) * K + kg] : 0.f;
            }
            for (int i = t; i < 2048; i += 256) {
                int kk = i >> 7, c = i & 127, kg = k0 + kk;
                Ws[kk][c] = (kg < K && (cb + c) < J.N) ? W[(size_t)kg * J.N + cb + c] : 0.f;
            }
            __syncthreads();
            #pragma unroll
            for (int kk = 0; kk < 16; kk++) {
                float4 w4 = *(float4*)&Ws[kk][cg * 4];
                #pragma unroll
                for (int i = 0; i < 8; i++) {
                    float a = As[kk][rg * 8 + i];
                    acc[i][0] += a * w4.x; acc[i][1] += a * w4.y;
                    acc[i][2] += a * w4.z; acc[i][3] += a * w4.w;
                }
            }
            __syncthreads();
        }
    }
    #pragma unroll
    for (int i = 0; i < 8; i++) {
        int row = rb + rg * 8 + i;
        float dscale = J.degp ? 1.f / fmaxf(J.degp[row], 1.f) : 1.f;
        #pragma unroll
        for (int j = 0; j < 4; j++) {
            int col = cb + cg * 4 + j;
            if (col < J.N) {
                float v = acc[i][j];
                if (J.bias) v += J.bias[col];
                if (J.addD) v += J.addD[(size_t)row * J.N + col] * dscale;
                if (J.relu) v = fmaxf(v, 0.f);
                J.C[(size_t)row * J.N + col] = v;
            }
        }
    }
}

// ---------- fused prep: rownorms + matvecs(+max) ----------
__global__ void prep_all(
    const float* __restrict__ ha, const float* __restrict__ hp,
    const float* __restrict__ ht, const float* __restrict__ hc,
    float* __restrict__ an, float* __restrict__ snp,
    float* __restrict__ snt, float* __restrict__ snc,
    const float* __restrict__ gp, const float* __restrict__ gt, const float* __restrict__ gc,
    const float* __restrict__ wdv, const float* __restrict__ gas,
    float* __restrict__ ald, float* __restrict__ alsp, float* __restrict__ alst,
    float* __restrict__ alsc, unsigned* __restrict__ mxsEnc)
{
    int m = blockIdx.x, t = threadIdx.x;
    __shared__ float ws[4];
    if (m < 18432) {
        const float* X; float* Y; int r;
        if (m < 4096)       { X = ha; Y = an;  r = m; }
        else if (m < 12288) { X = hp; Y = snp; r = m - 4096; }
        else if (m < 16384) { X = ht; Y = snt; r = m - 12288; }
        else                { X = hc; Y = snc; r = m - 16384; }
        float v = X[(size_t)r * 128 + t];
        float s = v * v;
        #pragma unroll
        for (int o = 16; o; o >>= 1) s += __shfl_xor_sync(0xffffffffu, s, o);
        if ((t & 31) == 0) ws[t >> 5] = s;
        __syncthreads();
        float tot = ws[0] + ws[1] + ws[2] + ws[3];
        Y[(size_t)r * 128 + t] = v / fmaxf(sqrtf(tot), 1e-12f);
    } else {
        int m2 = m - 18432;
        const float* X; const float* vec; float* y; int r; int mxi = -1;
        if (m2 < 12288) {
            int tpe = m2 >> 12;
            X = ha; vec = wdv + tpe * 128; y = ald + tpe * NA; r = m2 & 4095;
        } else {
            int m3 = m2 - 12288;
            if (m3 < 8192)       { X = gp; vec = gas;       y = alsp; r = m3;         mxi = 0; }
            else if (m3 < 12288) { X = gt; vec = gas + 128; y = alst; r = m3 - 8192;  mxi = 1; }
            else                 { X = gc; vec = gas + 256; y = alsc; r = m3 - 12288; mxi = 2; }
        }
        float s = X[(size_t)r * 128 + t] * vec[t];
        #pragma unroll
        for (int o = 16; o; o >>= 1) s += __shfl_xor_sync(0xffffffffu, s, o);
        if ((t & 31) == 0) ws[t >> 5] = s;
        __syncthreads();
        if (t == 0) {
            float tot = ws[0] + ws[1] + ws[2] + ws[3];
            y[r] = tot;
            if (mxi >= 0) atomicMax(&mxsEnc[mxi], enc_f(tot));
        }
    }
}

// ---------- hetero flush ----------
__device__ __forceinline__ void hetero_flush(
    float* __restrict__ acc, float* __restrict__ deng, const float* __restrict__ sDEN,
    ull (&num2)[4][4], int curType, int r0g, int rg, int cg)
{
    float* accT = acc + (size_t)curType * NA * 128;
    #pragma unroll
    for (int i = 0; i < 4; i++) {
        size_t row = (size_t)(r0g + rg * 4 + i) * 128;
        float2 v0 = unpack2(num2[i][0]), v1 = unpack2(num2[i][1]);
        float2 v2 = unpack2(num2[i][2]), v3 = unpack2(num2[i][3]);
        size_t b1 = row + cg * 4, b2 = row + 64 + cg * 4;
        atomicAdd(&accT[b1 + 0], v0.x); atomicAdd(&accT[b1 + 1], v0.y);
        atomicAdd(&accT[b1 + 2], v1.x); atomicAdd(&accT[b1 + 3], v1.y);
        atomicAdd(&accT[b2 + 0], v2.x); atomicAdd(&accT[b2 + 1], v2.y);
        atomicAdd(&accT[b2 + 2], v3.x); atomicAdd(&accT[b2 + 3], v3.y);
    }
    if (cg == 0) {
        #pragma unroll
        for (int i = 0; i < 4; i++)
            atomicAdd(&deng[curType * NA + r0g + rg * 4 + i], sDEN[rg * 4 + i]);
    }
}

// ---------- persistent fused hetero GAT (f32x2), grid = 304 balanced ----------
#define HET_GRID 304
__global__ __launch_bounds__(256, 2) void hetero_kernel(
    const float* __restrict__ an, const float* __restrict__ ald3,
    const unsigned* __restrict__ mxsEnc,
    const float* __restrict__ snp, const float* __restrict__ gp, const float* __restrict__ alsp,
    const float* __restrict__ snt, const float* __restrict__ gt, const float* __restrict__ alst,
    const float* __restrict__ snc, const float* __restrict__ gc, const float* __restrict__ alsc,
    float* __restrict__ acc, float* __restrict__ deng)
{
    extern __shared__ char smraw[];
    float* sAN  = (float*)smraw;             // 64x128 f  (32768B)
    ull*   sB2  = (ull*)(smraw + 32768);     // 64x34 ull (17408B)
    float* sHS  = (float*)(smraw + 50176);   // 32x128 f  (16384B)
    ull*   sW2  = (ull*)(smraw + 66560);     // 64x33 ull (16896B)
    float* sALD = (float*)(smraw + 83456);
    float* sDEN = (float*)(smraw + 83712);
    float* sALS = (float*)(smraw + 83968);
    ull* sANu = (ull*)sAN;
    ull* sHSu = (ull*)sHS;

    const int TOT = 28672;
    int bid = blockIdx.x;
    int cs = (int)(((long long)bid * TOT) / HET_GRID);
    int ce = (int)(((long long)(bid + 1) * TOT) / HET_GRID);
    int t = threadIdx.x, cg = t & 15, rg = t >> 4;

    int curType = -1, curAb = -1, r0g = 0;
    float mx = 0.f;
    const float *sn = snp, *hs = gp, *als = alsp;
    ull num2[4][4];

    for (int c = cs; c < ce; c++) {
        int type, ab, ch;
        if (c < 16384)      { type = 0; ab = c >> 8; ch = c & 255; }
        else if (c < 24576) { int c2 = c - 16384; type = 1; ab = c2 >> 7; ch = c2 & 127; }
        else                { int c2 = c - 24576; type = 2; ab = c2 >> 6; ch = c2 & 63; }
        int j0 = ch << 5;

        if (type != curType || ab != curAb) {
            if (curType >= 0) {
                hetero_flush(acc, deng, sDEN, num2, curType, r0g, rg, cg);
                __syncthreads();
            }
            curType = type; curAb = ab; r0g = ab << 6;
            if (type == 0)      { sn = snp; hs = gp; als = alsp; }
            else if (type == 1) { sn = snt; hs = gt; als = alst; }
            else                { sn = snc; hs = gc; als = alsc; }
            mx = dec_f(mxsEnc[type]);
            for (int i = t; i < 2048; i += 256) {
                int r = i >> 5, q = i & 31;
                *(float4*)&sAN[r * 128 + q * 4] =
                    *(const float4*)&an[(size_t)(r0g + r) * 128 + q * 4];
            }
            if (t < 64) { sALD[t] = ald3[type * NA + r0g + t]; sDEN[t] = 0.f; }
            #pragma unroll
            for (int i = 0; i < 4; i++)
                #pragma unroll
                for (int p = 0; p < 4; p++) num2[i][p] = 0ull;
            __syncthreads();
        }

        // load SN (k-pair packed) + HS chunk
        for (int i = t; i < 1024; i += 256) {
            int j = i >> 5, q = i & 31;
            float4 v = *(const float4*)&sn[(size_t)(j0 + j) * 128 + q * 4];
            sB2[(2 * q) * 34 + j]     = pack2(v.x, v.y);
            sB2[(2 * q + 1) * 34 + j] = pack2(v.z, v.w);
            *(float4*)&sHS[j * 128 + q * 4] =
                *(const float4*)&hs[(size_t)(j0 + j) * 128 + q * 4];
        }
        if (t < 32) sALS[t] = als[j0 + t];
        __syncthreads();

        // phase 1: packed-k dot products
        ull S2[4][2];
        #pragma unroll
        for (int i = 0; i < 4; i++) { S2[i][0] = 0ull; S2[i][1] = 0ull; }
        #pragma unroll 4
        for (int q = 0; q < 32; q++) {
            ulonglong2 b0 = *(ulonglong2*)&sB2[(2 * q) * 34 + cg * 2];
            ulonglong2 b1 = *(ulonglong2*)&sB2[(2 * q + 1) * 34 + cg * 2];
            #pragma unroll
            for (int i = 0; i < 4; i++) {
                ulonglong2 a = *(ulonglong2*)&sANu[(rg * 4 + i) * 64 + 2 * q];
                fma2(S2[i][0], a.x, b0.x); fma2(S2[i][1], a.x, b0.y);
                fma2(S2[i][0], a.y, b1.x); fma2(S2[i][1], a.y, b1.y);
            }
        }

        // phase 1.5: weights + denominators
        float rsum[4];
        #pragma unroll
        for (int i = 0; i < 4; i++) {
            float aldr = sALD[rg * 4 + i];
            float tm = aldr + mx;
            float mrow = tm >= 0.f ? tm : 0.2f * tm;
            rsum[i] = 0.f;
            #pragma unroll
            for (int jj = 0; jj < 2; jj++) {
                float2 sp = unpack2(S2[i][jj]);
                float sval = sp.x + sp.y;
                float w = 0.f;
                int jgl = j0 + cg * 2 + jj;
                if (sval > 0.1f && (r0g + rg * 4 + i) != jgl) {
                    float e0 = aldr + sALS[cg * 2 + jj];
                    float e = e0 >= 0.f ? e0 : 0.2f * e0;
                    w = __expf(e - mrow);
                }
                sW2[(rg * 4 + i) * 33 + cg * 2 + jj] = pack2(w, w);
                rsum[i] += w;
            }
        }
        #pragma unroll
        for (int o = 1; o < 16; o <<= 1)
            #pragma unroll
            for (int i = 0; i < 4; i++)
                rsum[i] += __shfl_xor_sync(0xffffffffu, rsum[i], o);
        if (cg == 0)
            #pragma unroll
            for (int i = 0; i < 4; i++) sDEN[rg * 4 + i] += rsum[i];
        __syncthreads();

        // phase 2: num += W @ HS (packed columns), skipping all-zero weight rows.
        // ~88% of weights are 0 (sim<=0.1); a warp covers 8 author rows, so with
        // prob ~0.88^8 the whole warp skips the loads+FMAs for this src column.
        #pragma unroll 2
        for (int j = 0; j < 32; j++) {
            ull wp0 = sW2[(rg * 4 + 0) * 33 + j];
            ull wp1 = sW2[(rg * 4 + 1) * 33 + j];
            ull wp2 = sW2[(rg * 4 + 2) * 33 + j];
            ull wp3 = sW2[(rg * 4 + 3) * 33 + j];
            if ((wp0 | wp1 | wp2 | wp3) == 0ull) continue;
            ulonglong2 hA = *(ulonglong2*)&sHSu[j * 64 + cg * 2];
            ulonglong2 hB = *(ulonglong2*)&sHSu[j * 64 + 32 + cg * 2];
            fma2(num2[0][0], wp0, hA.x); fma2(num2[0][1], wp0, hA.y);
            fma2(num2[0][2], wp0, hB.x); fma2(num2[0][3], wp0, hB.y);
            fma2(num2[1][0], wp1, hA.x); fma2(num2[1][1], wp1, hA.y);
            fma2(num2[1][2], wp1, hB.x); fma2(num2[1][3], wp1, hB.y);
            fma2(num2[2][0], wp2, hA.x); fma2(num2[2][1], wp2, hA.y);
            fma2(num2[2][2], wp2, hB.x); fma2(num2[2][3], wp2, hB.y);
            fma2(num2[3][0], wp3, hA.x); fma2(num2[3][1], wp3, hA.y);
            fma2(num2[3][2], wp3, hB.x); fma2(num2[3][3], wp3, hB.y);
        }
        __syncthreads();
    }
    if (curType >= 0)
        hetero_flush(acc, deng, sDEN, num2, curType, r0g, rg, cg);
}

__global__ void finalize_kernel(float* __restrict__ acc, const float* __restrict__ den,
                                const float* __restrict__ gb) {
    int idx = blockIdx.x * blockDim.x + threadIdx.x;
    if (idx >= 3 * NA * 128) return;
    int c = idx & 127, dr = idx >> 7, type = idx >> 19;
    float d = den[dr], b = gb[type * 128 + c];
    acc[idx] = (d > 0.f) ? acc[idx] / d + b : b;
}

__global__ void attscore_kernel(const float* __restrict__ heter, const float* __restrict__ xt,
                                const float* __restrict__ Watt, const float* __restrict__ atts,
                                float* __restrict__ ssum) {
    int set = blockIdx.y;
    const float* X = (set < 3) ? heter + (size_t)set * NA * 128 : xt;
    int rb = blockIdx.x * 4, t = threadIdx.x, c = t & 63;
    __shared__ float xs[4][128];
    for (int i = t; i < 512; i += 256)
        xs[i >> 7][i & 127] = X[(size_t)(rb + (i >> 7)) * 128 + (i & 127)];
    __syncthreads();
    const float* xr = xs[t >> 6];
    float dot = 0.f;
    #pragma unroll 8
    for (int k = 0; k < 128; k++) dot += xr[k] * Watt[k * 64 + c];
    float val = (1.f / (1.f + __expf(-dot))) * atts[set * 64 + c];
    #pragma unroll
    for (int o = 16; o; o >>= 1) val += __shfl_xor_sync(0xffffffffu, val, o);
    __shared__ float ps[8];
    if ((t & 31) == 0) ps[t >> 5] = val;
    __syncthreads();
    if (t == 0) {
        float s = 0.f;
        #pragma unroll
        for (int i = 0; i < 8; i++) s += ps[i];
        atomicAdd(&ssum[set], s);
    }
}

__global__ void alpha_kernel(const float* __restrict__ ssum, float* __restrict__ alpha) {
    if (threadIdx.x == 0) {
        float s[4], m = -3e38f;
        for (int i = 0; i < 4; i++) { s[i] = ssum[i] / (float)NA; m = fmaxf(m, s[i]); }
        float e[4], tot = 0.f;
        for (int i = 0; i < 4; i++) { e[i] = expf(s[i] - m); tot += e[i]; }
        for (int i = 0; i < 4; i++) alpha[i] = e[i] / tot;
    }
}

__global__ void xatt_kernel(const float* __restrict__ heter, const float* __restrict__ xt,
                            const float* __restrict__ alpha, float* __restrict__ out) {
    int idx = blockIdx.x * blockDim.x + threadIdx.x;
    if (idx >= NA * 128) return;
    out[idx] = alpha[0] * heter[idx] + alpha[1] * heter[NA * 128 + idx] +
               alpha[2] * heter[2 * NA * 128 + idx] + alpha[3] * xt[idx];
}

__global__ void deg_kernel(const int* __restrict__ dst, float* __restrict__ deg, int E) {
    int e = blockIdx.x * blockDim.x + threadIdx.x;
    if (e < E) atomicAdd(&deg[dst[e]], 1.0f);
}

__global__ void scatter_kernel(const float* __restrict__ X, const int* __restrict__ src,
                               const int* __restrict__ dst, float* __restrict__ AGG,
                               int E, int C) {
    int idx = blockIdx.x * blockDim.x + threadIdx.x;
    int per = C >> 2;
    if (idx >= E * per) return;
    int e = idx / per, q = idx - e * per;
    int s = src[e], d = dst[e];
    float4 v = *(const float4*)&X[(size_t)s * C + q * 4];
    float* o = &AGG[(size_t)d * C + q * 4];
    atomicAdd(o + 0, v.x); atomicAdd(o + 1, v.y);
    atomicAdd(o + 2, v.z); atomicAdd(o + 3, v.w);
}

__global__ void rowdiv_kernel(float* __restrict__ AGG, const float* __restrict__ deg,
                              int n, int C) {
    int idx = blockIdx.x * blockDim.x + threadIdx.x;
    if (idx >= n) return;
    AGG[idx] = AGG[idx] / fmaxf(deg[idx / C], 1.0f);
}

extern "C" void kernel_launch(void* const* d_in, const int* in_sizes, int n_in,
                              void* d_out, int out_size) {
    const float* x_ma = (const float*)d_in[0];
    const float* x_mp = (const float*)d_in[1];
    const float* x_mt = (const float*)d_in[2];
    const float* x_mc = (const float*)d_in[3];
    const float* x_ia = (const float*)d_in[4];
    const int*   edge = (const int*)d_in[5];
    const float* Wla  = (const float*)d_in[6];  const float* bla  = (const float*)d_in[7];
    const float* Wlp  = (const float*)d_in[8];  const float* blp  = (const float*)d_in[9];
    const float* Wlt  = (const float*)d_in[10]; const float* blt  = (const float*)d_in[11];
    const float* Wlc  = (const float*)d_in[12]; const float* blc  = (const float*)d_in[13];
    const float* Wltg = (const float*)d_in[14]; const float* bltg = (const float*)d_in[15];
    const float* gWs  = (const float*)d_in[16];
    const float* gWd  = (const float*)d_in[17];
    const float* gas  = (const float*)d_in[18];
    const float* gad  = (const float*)d_in[19];
    const float* gb   = (const float*)d_in[20];
    const float* Watt = (const float*)d_in[21];
    const float* atts = (const float*)d_in[22];
    const float* W1l  = (const float*)d_in[23]; const float* b1 = (const float*)d_in[24];
    const float* W1r  = (const float*)d_in[25];
    const float* W2l  = (const float*)d_in[26]; const float* b2 = (const float*)d_in[27];
    const float* W2r  = (const float*)d_in[28];

    int E = in_sizes[5] / 2;
    int Ka = in_sizes[0] / NA, Kp = in_sizes[1] / NP, Kt = in_sizes[2] / NT;
    int Kc = in_sizes[3] / NC, Kg = in_sizes[4] / NA;

    float* out_x   = (float*)d_out;
    float* out_att = (float*)d_out + (size_t)NA * 64;

    float *ha,*hp,*ht,*hc,*xt,*an,*snp,*snt,*snc,*gp,*gt,*gc;
    float *alsp,*alst,*alsc,*ald,*wdv,*acc,*den,*ssum,*alpha,*agg1,*deg,*h1,*q,*aggq;
    unsigned* mxsEnc;
    cudaGetSymbolAddress((void**)&ha,g_ha);   cudaGetSymbolAddress((void**)&hp,g_hp);
    cudaGetSymbolAddress((void**)&ht,g_ht);   cudaGetSymbolAddress((void**)&hc,g_hc);
    cudaGetSymbolAddress((void**)&xt,g_xt);   cudaGetSymbolAddress((void**)&an,g_an);
    cudaGetSymbolAddress((void**)&snp,g_snp); cudaGetSymbolAddress((void**)&snt,g_snt);
    cudaGetSymbolAddress((void**)&snc,g_snc); cudaGetSymbolAddress((void**)&gp,g_gp);
    cudaGetSymbolAddress((void**)&gt,g_gt);   cudaGetSymbolAddress((void**)&gc,g_gc);
    cudaGetSymbolAddress((void**)&alsp,g_alsp); cudaGetSymbolAddress((void**)&alst,g_alst);
    cudaGetSymbolAddress((void**)&alsc,g_alsc); cudaGetSymbolAddress((void**)&ald,g_ald);
    cudaGetSymbolAddress((void**)&wdv,g_wdv);   cudaGetSymbolAddress((void**)&mxsEnc,g_mxsEnc);
    cudaGetSymbolAddress((void**)&acc,g_acc);   cudaGetSymbolAddress((void**)&den,g_den);
    cudaGetSymbolAddress((void**)&ssum,g_ssum); cudaGetSymbolAddress((void**)&alpha,g_alpha);
    cudaGetSymbolAddress((void**)&agg1,g_agg1); cudaGetSymbolAddress((void**)&deg,g_deg);
    cudaGetSymbolAddress((void**)&h1,g_h1);     cudaGetSymbolAddress((void**)&q,g_q);
    cudaGetSymbolAddress((void**)&aggq,g_aggq);

    auto mkjob = [](const float*A,const float*W,const float*A2,const float*W2,
                    const float*bias,const float*addD,const float*degp,float*C,
                    int M,int K,int K2,int N,int relu,int colBlks,int blkStart){
        LJob J; J.A=A;J.W=W;J.A2=A2;J.W2=W2;J.bias=bias;J.addD=addD;J.degp=degp;J.C=C;
        J.M=M;J.K=K;J.K2=K2;J.N=N;J.relu=relu;J.colBlks=colBlks;J.blkStart=blkStart;
        return J;
    };

    wvec_kernel<<<3,128>>>(gWd, gad, wdv);
    zero_all<<<9281,256>>>(acc, agg1, aggq, den, deg, ssum, mxsEnc);
    {
        LJobs B; B.n = 5;
        B.j[0] = mkjob(x_ma, Wla,  0,0, bla,  0,0, ha, NA, Ka, 0, 128, 0, 1, 0);
        B.j[1] = mkjob(x_mp, Wlp,  0,0, blp,  0,0, hp, NP, Kp, 0, 128, 0, 1, 64);
        B.j[2] = mkjob(x_mt, Wlt,  0,0, blt,  0,0, ht, NT, Kt, 0, 128, 0, 1, 192);
        B.j[3] = mkjob(x_mc, Wlc,  0,0, blc,  0,0, hc, NC, Kc, 0, 128, 0, 1, 256);
        B.j[4] = mkjob(x_ia, Wltg, 0,0, bltg, 0,0, xt, NA, Kg, 0, 128, 0, 1, 288);
        lin_batch<<<352,256>>>(B);
    }
    {
        LJobs B; B.n = 3;
        B.j[0] = mkjob(hp, gWs + 0*16384, 0,0, 0,0,0, gp, NP, 128, 0, 128, 0, 1, 0);
        B.j[1] = mkjob(ht, gWs + 1*16384, 0,0, 0,0,0, gt, NT, 128, 0, 128, 0, 1, 128);
        B.j[2] = mkjob(hc, gWs + 2*16384, 0,0, 0,0,0, gc, NC, 128, 0, 128, 0, 1, 192);
        lin_batch<<<224,256>>>(B);
    }
    prep_all<<<45056,128>>>(ha, hp, ht, hc, an, snp, snt, snc,
                            gp, gt, gc, wdv, gas, ald, alsp, alst, alsc, mxsEnc);
    cudaFuncSetAttribute(hetero_kernel, cudaFuncAttributeMaxDynamicSharedMemorySize, 84096);
    hetero_kernel<<<HET_GRID,256,84096>>>(an, ald, mxsEnc, snp, gp, alsp,
                                          snt, gt, alst, snc, gc, alsc, acc, den);
    finalize_kernel<<<(3*NA*128)/256,256>>>(acc, den, gb);
    attscore_kernel<<<dim3(NA/4,4),256>>>(acc, xt, Watt, atts, ssum);
    alpha_kernel<<<1,32>>>(ssum, alpha);
    xatt_kernel<<<(NA*128)/256,256>>>(acc, xt, alpha, out_att);
    deg_kernel<<<(E+255)/256,256>>>(edge + E, deg, E);
    scatter_kernel<<<(E*32)/256,256>>>(ha, edge, edge + E, agg1, E, 128);
    rowdiv_kernel<<<(NA*128)/256,256>>>(agg1, deg, NA*128, 128);
    {
        LJobs B; B.n = 1;
        B.j[0] = mkjob(agg1, W1l, ha, W1r, b1, 0,0, h1, NA, 128, 128, 256, 1, 2, 0);
        lin_batch<<<128,256>>>(B);
    }
    {
        LJobs B; B.n = 1;
        B.j[0] = mkjob(h1, W2l, 0,0, 0,0,0, q, NA, 256, 0, 64, 0, 1, 0);
        lin_batch<<<64,256>>>(B);
    }
    scatter_kernel<<<(E*16)/256,256>>>(q, edge, edge + E, aggq, E, 64);
    {
        LJobs B; B.n = 1;
        B.j[0] = mkjob(h1, W2r, 0,0, b2, aggq, deg, out_x, NA, 256, 0, 64, 0, 1, 0);
        lin_batch<<<64,256>>>(B);
    }
}

// round 9
// speedup vs baseline: 2.5962x; 1.7827x over previous
#include <cuda_runtime.h>
#include <cuda_bf16.h>
#include <math.h>

#define NA 4096
#define NP 8192
#define NT 4096
#define NC 2048
typedef unsigned long long ull;

// ---------------- device scratch ----------------
__device__ float g_ha[NA*128];
__device__ float g_hp[NP*128];
__device__ float g_ht[NT*128];
__device__ float g_hc[NC*128];
__device__ float g_xt[NA*128];
__device__ __nv_bfloat16 g_anh[NA*128];
__device__ __nv_bfloat16 g_anl[NA*128];
__device__ __nv_bfloat16 g_snh[(NP+NT+NC)*128];
__device__ __nv_bfloat16 g_snl[(NP+NT+NC)*128];
__device__ __nv_bfloat16 g_hsT[(NP+NT+NC)*128];
__device__ float g_gp[NP*128];
__device__ float g_gt[NT*128];
__device__ float g_gc[NC*128];
__device__ float g_alsp[NP];
__device__ float g_alst[NT];
__device__ float g_alsc[NC];
__device__ float g_ald[3*NA];
__device__ float g_wdv[3*128];
__device__ unsigned g_mxsEnc[3];
__device__ float g_acc[3*NA*128];
__device__ float g_den[3*NA];
__device__ float g_ssum[4];
__device__ float g_alpha[4];
__device__ float g_agg1[NA*128];
__device__ float g_deg[NA];
__device__ float g_h1[NA*256];
__device__ float g_q[NA*64];
__device__ float g_aggq[NA*64];

__device__ __forceinline__ unsigned enc_f(float f) {
    unsigned b = __float_as_uint(f);
    return (b & 0x80000000u) ? ~b : (b | 0x80000000u);
}
__device__ __forceinline__ float dec_f(unsigned u) {
    unsigned b = (u & 0x80000000u) ? (u ^ 0x80000000u) : ~u;
    return __uint_as_float(b);
}
__device__ __forceinline__ unsigned smem_u32(const void* p) {
    unsigned a;
    asm("{ .reg .u64 t; cvta.to.shared.u64 t, %1; cvt.u32.u64 %0, t; }" : "=r"(a) : "l"(p));
    return a;
}
__device__ __forceinline__ void ldsm4(unsigned addr, unsigned& r0, unsigned& r1,
                                      unsigned& r2, unsigned& r3) {
    asm volatile("ldmatrix.sync.aligned.m8n8.x4.shared.b16 {%0,%1,%2,%3},[%4];"
                 : "=r"(r0), "=r"(r1), "=r"(r2), "=r"(r3) : "r"(addr));
}
__device__ __forceinline__ void mma_bf16(float* d, unsigned a0, unsigned a1,
                                         unsigned a2, unsigned a3,
                                         unsigned b0, unsigned b1) {
    asm volatile(
        "mma.sync.aligned.m16n8k16.row.col.f32.bf16.bf16.f32 "
        "{%0,%1,%2,%3},{%4,%5,%6,%7},{%8,%9},{%0,%1,%2,%3};"
        : "+f"(d[0]), "+f"(d[1]), "+f"(d[2]), "+f"(d[3])
        : "r"(a0), "r"(a1), "r"(a2), "r"(a3), "r"(b0), "r"(b1));
}

// ---------------- fused zero init ----------------
__global__ void zero_all(float* __restrict__ acc, float* __restrict__ agg1,
                         float* __restrict__ aggq, float* __restrict__ den,
                         float* __restrict__ deg, float* __restrict__ ssum,
                         unsigned* __restrict__ mxsEnc) {
    int i = blockIdx.x * 256 + threadIdx.x;
    if (i < 1572864) { acc[i] = 0.f; return; }
    i -= 1572864; if (i < 524288) { agg1[i] = 0.f; return; }
    i -= 524288;  if (i < 262144) { aggq[i] = 0.f; return; }
    i -= 262144;  if (i < 12288)  { den[i] = 0.f; return; }
    i -= 12288;   if (i < 4096)   { deg[i] = 0.f; return; }
    i -= 4096;    if (i < 4)      { ssum[i] = 0.f; return; }
    i -= 4;       if (i < 3)      mxsEnc[i] = enc_f(-3.0e38f);
}

// ---------------- wdv ----------------
__global__ void wvec_kernel(const float* __restrict__ W3, const float* __restrict__ a3,
                            float* __restrict__ out3) {
    int i = blockIdx.x, k = threadIdx.x;
    __shared__ float sa[128];
    sa[k] = a3[i * 128 + k];
    __syncthreads();
    const float* W = W3 + (size_t)i * 16384 + (size_t)k * 128;
    float s = 0.f;
    #pragma unroll 8
    for (int c = 0; c < 128; c++) s += W[c] * sa[c];
    out3[i * 128 + k] = s;
}

// ---------------- batched linear ----------------
struct LJob {
    const float *A, *W, *A2, *W2, *bias, *addD, *degp;
    float* C;
    int M, K, K2, N, relu, colBlks, blkStart;
};
struct LJobs { LJob j[5]; int n; };

__global__ __launch_bounds__(256) void lin_batch(LJobs P) {
    int bid = blockIdx.x;
    int sel = 0;
    #pragma unroll
    for (int i = 1; i < 5; i++)
        if (i < P.n && bid >= P.j[i].blkStart) sel = i;
    LJob J = P.j[sel];
    int rel = bid - J.blkStart;
    int rb = (rel / J.colBlks) * 64, cb = (rel % J.colBlks) * 128;

    __shared__ float As[16][64];
    __shared__ float Ws[16][128];
    int t = threadIdx.x, cg = t & 31, rg = t >> 5;
    float acc[8][4];
    #pragma unroll
    for (int i = 0; i < 8; i++)
        #pragma unroll
        for (int j = 0; j < 4; j++) acc[i][j] = 0.f;

    #pragma unroll 1
    for (int ph = 0; ph < 2; ph++) {
        const float* A = ph ? J.A2 : J.A;
        const float* W = ph ? J.W2 : J.W;
        int K = ph ? J.K2 : J.K;
        if (!A) break;
        for (int k0 = 0; k0 < K; k0 += 16) {
            for (int i = t; i < 1024; i += 256) {
                int r = i >> 4, kk = i & 15, kg = k0 + kk;
                As[kk][r] = (kg < K) ? A[(size_t)(rb + r) * K + kg] : 0.f;
            }
            for (int i = t; i < 2048; i += 256) {
                int kk = i >> 7, c = i & 127, kg = k0 + kk;
                Ws[kk][c] = (kg < K && (cb + c) < J.N) ? W[(size_t)kg * J.N + cb + c] : 0.f;
            }
            __syncthreads();
            #pragma unroll
            for (int kk = 0; kk < 16; kk++) {
                float4 w4 = *(float4*)&Ws[kk][cg * 4];
                #pragma unroll
                for (int i = 0; i < 8; i++) {
                    float a = As[kk][rg * 8 + i];
                    acc[i][0] += a * w4.x; acc[i][1] += a * w4.y;
                    acc[i][2] += a * w4.z; acc[i][3] += a * w4.w;
                }
            }
            __syncthreads();
        }
    }
    #pragma unroll
    for (int i = 0; i < 8; i++) {
        int row = rb + rg * 8 + i;
        float dscale = J.degp ? 1.f / fmaxf(J.degp[row], 1.f) : 1.f;
        #pragma unroll
        for (int j = 0; j < 4; j++) {
            int col = cb + cg * 4 + j;
            if (col < J.N) {
                float v = acc[i][j];
                if (J.bias) v += J.bias[col];
                if (J.addD) v += J.addD[(size_t)row * J.N + col] * dscale;
                if (J.relu) v = fmaxf(v, 0.f);
                J.C[(size_t)row * J.N + col] = v;
            }
        }
    }
}

// ---------------- fused prep: rownorm(+split) + matvec(+max) + hsT ----------------
__global__ void prep_all(
    const float* __restrict__ ha, const float* __restrict__ hp,
    const float* __restrict__ ht, const float* __restrict__ hc,
    __nv_bfloat16* __restrict__ anh, __nv_bfloat16* __restrict__ anl,
    __nv_bfloat16* __restrict__ snh, __nv_bfloat16* __restrict__ snl,
    const float* __restrict__ gp, const float* __restrict__ gt, const float* __restrict__ gc,
    const float* __restrict__ wdv, const float* __restrict__ gas,
    float* __restrict__ ald, float* __restrict__ alsp, float* __restrict__ alst,
    float* __restrict__ alsc, unsigned* __restrict__ mxsEnc,
    __nv_bfloat16* __restrict__ hsT)
{
    int m = blockIdx.x, t = threadIdx.x;
    __shared__ float ws[4];
    __shared__ float tile[32][33];
    if (m < 18432) {
        const float* X; int r; int isAu = 0; size_t off = 0;
        if (m < 4096)       { X = ha; r = m; isAu = 1; }
        else if (m < 12288) { X = hp; r = m - 4096;  off = 0; }
        else if (m < 16384) { X = ht; r = m - 12288; off = (size_t)NP * 128; }
        else                { X = hc; r = m - 16384; off = (size_t)(NP + NT) * 128; }
        float v = X[(size_t)r * 128 + t];
        float s = v * v;
        #pragma unroll
        for (int o = 16; o; o >>= 1) s += __shfl_xor_sync(0xffffffffu, s, o);
        if ((t & 31) == 0) ws[t >> 5] = s;
        __syncthreads();
        float tot = ws[0] + ws[1] + ws[2] + ws[3];
        float y = v / fmaxf(sqrtf(tot), 1e-12f);
        __nv_bfloat16 hi = __float2bfloat16(y);
        __nv_bfloat16 lo = __float2bfloat16(y - __bfloat162float(hi));
        if (isAu) {
            anh[(size_t)r * 128 + t] = hi;
            anl[(size_t)r * 128 + t] = lo;
        } else {
            snh[off + (size_t)r * 128 + t] = hi;
            snl[off + (size_t)r * 128 + t] = lo;
        }
    } else if (m < 45056) {
        int m2 = m - 18432;
        const float* X; const float* vec; float* y; int r; int mxi = -1;
        if (m2 < 12288) {
            int tpe = m2 >> 12;
            X = ha; vec = wdv + tpe * 128; y = ald + tpe * NA; r = m2 & 4095;
        } else {
            int m3 = m2 - 12288;
            if (m3 < 8192)       { X = gp; vec = gas;       y = alsp; r = m3;         mxi = 0; }
            else if (m3 < 12288) { X = gt; vec = gas + 128; y = alst; r = m3 - 8192;  mxi = 1; }
            else                 { X = gc; vec = gas + 256; y = alsc; r = m3 - 12288; mxi = 2; }
        }
        float s = X[(size_t)r * 128 + t] * vec[t];
        #pragma unroll
        for (int o = 16; o; o >>= 1) s += __shfl_xor_sync(0xffffffffu, s, o);
        if ((t & 31) == 0) ws[t >> 5] = s;
        __syncthreads();
        if (t == 0) {
            float tot = ws[0] + ws[1] + ws[2] + ws[3];
            y[r] = tot;
            if (mxi >= 0) atomicMax(&mxsEnc[mxi], enc_f(tot));
        }
    } else {
        int ti = m - 45056;
        const float* X; __nv_bfloat16* O; int Ns2, s0, d0;
        if (ti < 1024)      { X = gp; O = hsT;                          Ns2 = NP; s0 = (ti & 255) * 32; d0 = (ti >> 8) * 32; }
        else if (ti < 1536) { int u = ti - 1024; X = gt; O = hsT + (size_t)128 * NP;        Ns2 = NT; s0 = (u & 127) * 32; d0 = (u >> 7) * 32; }
        else                { int u = ti - 1536; X = gc; O = hsT + (size_t)128 * (NP + NT); Ns2 = NC; s0 = (u & 63) * 32;  d0 = (u >> 6) * 32; }
        int tx = t & 31, ty = t >> 5;
        #pragma unroll
        for (int r = 0; r < 8; r++) {
            int rr = r * 4 + ty;
            tile[rr][tx] = X[(size_t)(s0 + rr) * 128 + d0 + tx];
        }
        __syncthreads();
        #pragma unroll
        for (int r = 0; r < 8; r++) {
            int dd = r * 4 + ty;
            O[(size_t)(d0 + dd) * Ns2 + s0 + tx] = __float2bfloat16(tile[tx][dd]);
        }
    }
}

// ---------------- HMMA hetero GAT ----------------
// Persistent grid 304, 256 thr (8 warps). Job = (type, 64-author block).
// Chunk = 64 src. Phase1: S[64x64] = split-bf16 mma (3 passes). Phase2:
// NUM[64x128] += W@HS^T (bf16 mma), acc in registers across chunks.
#define HET_GRID 304
#define SA_ANH 0
#define SA_ANL 17408
#define SA_SNH 34816
#define SA_SNL 52224
#define SA_HST 69632
#define SA_W   88064
#define SA_ALD 97280
#define SA_ALS 97536
#define SA_TOT 97792

__global__ __launch_bounds__(256, 2) void hetero_mma(
    const __nv_bfloat16* __restrict__ anh, const __nv_bfloat16* __restrict__ anl,
    const float* __restrict__ ald3, const unsigned* __restrict__ mxsEnc,
    const __nv_bfloat16* __restrict__ snh, const __nv_bfloat16* __restrict__ snl,
    const __nv_bfloat16* __restrict__ hsT,
    const float* __restrict__ alsp, const float* __restrict__ alst,
    const float* __restrict__ alsc,
    float* __restrict__ acc, float* __restrict__ deng)
{
    extern __shared__ char sm[];
    unsigned sb = smem_u32(sm);
    float* sALD = (float*)(sm + SA_ALD);
    float* sALS = (float*)(sm + SA_ALS);

    int t = threadIdx.x, lane = t & 31, warp = t >> 5;
    int mt = warp >> 1, nh = warp & 1;
    int ltile = lane >> 3, lrow = lane & 7;
    // ldmatrix lane-address components
    int rowA = mt * 16 + ((ltile & 1) << 3) + lrow;      // A tiles: t0 r0-7c0, t1 r8-15c0, t2 r0-7c8, t3 r8-15c8
    unsigned colA = (unsigned)((ltile >> 1) * 16);
    int rowBl = ((ltile >> 1) << 3) + lrow;              // B tiles: t0 n0-7k0, t1 n0-7k8, t2 n8-15k0, t3 n8-15k8
    unsigned colB = (unsigned)((ltile & 1) * 16);
    int crow = lane >> 2;                                 // C frag row (also +8)
    int ccol = (lane & 3) * 2;                            // C frag col pair

    const int TOTC = 14336;
    int cs = (int)(((long long)blockIdx.x * TOTC) / HET_GRID);
    int ce = (int)(((long long)(blockIdx.x + 1) * TOTC) / HET_GRID);

    int curType = -1, curAb = -1, r0g = 0;
    const __nv_bfloat16 *snhT = snh, *snlT = snl, *hsTT = hsT;
    const float* alsT = alsp;
    int Ns = NP;
    float mx = 0.f, ald0 = 0.f, ald1 = 0.f, mrow0 = 0.f, mrow1 = 0.f;
    float den0 = 0.f, den1 = 0.f;
    float acc2[8][4];

    for (int c = cs; c < ce; c++) {
        int type, ab, ch;
        if (c < 8192)       { type = 0; ab = c >> 7; ch = c & 127; }
        else if (c < 12288) { int u = c - 8192;  type = 1; ab = u >> 6; ch = u & 63; }
        else                { int u = c - 12288; type = 2; ab = u >> 5; ch = u & 31; }
        int j0 = ch << 6;

        if (type != curType || ab != curAb) {
            if (curType >= 0) {
                // flush NUM + den
                int gr0 = r0g + mt * 16 + crow;
                #pragma unroll
                for (int nt = 0; nt < 8; nt++) {
                    int d = nh * 64 + nt * 8 + ccol;
                    float* b0 = acc + ((size_t)curType * NA + gr0) * 128 + d;
                    float* b1 = acc + ((size_t)curType * NA + gr0 + 8) * 128 + d;
                    atomicAdd(b0, acc2[nt][0]); atomicAdd(b0 + 1, acc2[nt][1]);
                    atomicAdd(b1, acc2[nt][2]); atomicAdd(b1 + 1, acc2[nt][3]);
                }
                float d0 = den0 + __shfl_xor_sync(0xffffffffu, den0, 1);
                d0 += __shfl_xor_sync(0xffffffffu, d0, 2);
                float d1 = den1 + __shfl_xor_sync(0xffffffffu, den1, 1);
                d1 += __shfl_xor_sync(0xffffffffu, d1, 2);
                if ((lane & 3) == 0 && nh == 0) {
                    atomicAdd(deng + curType * NA + gr0, d0);
                    atomicAdd(deng + curType * NA + gr0 + 8, d1);
                }
                if ((lane & 3) == 0 && nh == 1) {
                    atomicAdd(deng + curType * NA + gr0, d0);
                    atomicAdd(deng + curType * NA + gr0 + 8, d1);
                }
            }
            curType = type; curAb = ab; r0g = ab << 6;
            if (type == 0)      { snhT = snh; snlT = snl; hsTT = hsT; alsT = alsp; Ns = NP; }
            else if (type == 1) { snhT = snh + (size_t)NP * 128; snlT = snl + (size_t)NP * 128;
                                  hsTT = hsT + (size_t)128 * NP; alsT = alst; Ns = NT; }
            else                { snhT = snh + (size_t)(NP + NT) * 128; snlT = snl + (size_t)(NP + NT) * 128;
                                  hsTT = hsT + (size_t)128 * (NP + NT); alsT = alsc; Ns = NC; }
            mx = dec_f(mxsEnc[type]);
            __syncthreads();  // prior chunk reads done before overwriting AN
            // load AN hi/lo [64][128] -> padded [64][136]
            for (int i = t; i < 1024; i += 256) {
                int r = i >> 4, q = i & 15;
                *(uint4*)(sm + SA_ANH + r * 272 + q * 16) =
                    *(const uint4*)(anh + (size_t)(r0g + r) * 128 + q * 8);
                *(uint4*)(sm + SA_ANL + r * 272 + q * 16) =
                    *(const uint4*)(anl + (size_t)(r0g + r) * 128 + q * 8);
            }
            if (t < 64) sALD[t] = ald3[type * NA + r0g + t];
            __syncthreads();
            ald0 = sALD[mt * 16 + crow];
            ald1 = sALD[mt * 16 + crow + 8];
            float tm0 = ald0 + mx; mrow0 = tm0 >= 0.f ? tm0 : 0.2f * tm0;
            float tm1 = ald1 + mx; mrow1 = tm1 >= 0.f ? tm1 : 0.2f * tm1;
            den0 = den1 = 0.f;
            #pragma unroll
            for (int nt = 0; nt < 8; nt++)
                #pragma unroll
                for (int p = 0; p < 4; p++) acc2[nt][p] = 0.f;
        }

        __syncthreads();  // prior chunk reads done before overwriting SN/HST
        // load SN hi/lo [64][128]->[64][136], HST [128][64]->[128][72]
        for (int i = t; i < 1024; i += 256) {
            int r = i >> 4, q = i & 15;
            *(uint4*)(sm + SA_SNH + r * 272 + q * 16) =
                *(const uint4*)(snhT + (size_t)(j0 + r) * 128 + q * 8);
            *(uint4*)(sm + SA_SNL + r * 272 + q * 16) =
                *(const uint4*)(snlT + (size_t)(j0 + r) * 128 + q * 8);
            int hd = i >> 3, hq = i & 7;
            *(uint4*)(sm + SA_HST + hd * 144 + hq * 16) =
                *(const uint4*)(hsTT + (size_t)hd * Ns + j0 + hq * 8);
        }
        if (t < 64) sALS[t] = alsT[j0 + t];
        __syncthreads();

        // phase 1: S = ANh·SNh^T + ANh·SNl^T + ANl·SNh^T
        float acc1[4][4];
        #pragma unroll
        for (int nt = 0; nt < 4; nt++)
            #pragma unroll
            for (int p = 0; p < 4; p++) acc1[nt][p] = 0.f;
        #pragma unroll 1
        for (int pass = 0; pass < 3; pass++) {
            unsigned abase = sb + (pass < 2 ? SA_ANH : SA_ANL);
            unsigned bbase = sb + (pass == 1 ? SA_SNL : SA_SNH);
            #pragma unroll
            for (int k = 0; k < 8; k++) {
                unsigned a0, a1, a2, a3;
                ldsm4(abase + (unsigned)rowA * 272 + colA + k * 32, a0, a1, a2, a3);
                #pragma unroll
                for (int ntp = 0; ntp < 2; ntp++) {
                    unsigned b0, b1, b2, b3;
                    ldsm4(bbase + (unsigned)(nh * 32 + ntp * 16 + rowBl) * 272 + colB + k * 32,
                          b0, b1, b2, b3);
                    mma_bf16(acc1[ntp * 2],     a0, a1, a2, a3, b0, b1);
                    mma_bf16(acc1[ntp * 2 + 1], a0, a1, a2, a3, b2, b3);
                }
            }
        }

        // phase 1.5: masked softmax weights -> bf16 -> smem W
        int gr0 = r0g + mt * 16 + crow;
        #pragma unroll
        for (int nt = 0; nt < 4; nt++) {
            int jl = nh * 32 + nt * 8 + ccol;
            int jg = j0 + jl;
            float als0 = sALS[jl], als1 = sALS[jl + 1];
            float e0 = ald0 + als0; e0 = e0 >= 0.f ? e0 : 0.2f * e0;
            float e1 = ald0 + als1; e1 = e1 >= 0.f ? e1 : 0.2f * e1;
            float f0 = ald1 + als0; f0 = f0 >= 0.f ? f0 : 0.2f * f0;
            float f1 = ald1 + als1; f1 = f1 >= 0.f ? f1 : 0.2f * f1;
            float w00 = (acc1[nt][0] > 0.1f && gr0 != jg)         ? __expf(e0 - mrow0) : 0.f;
            float w01 = (acc1[nt][1] > 0.1f && gr0 != jg + 1)     ? __expf(e1 - mrow0) : 0.f;
            float w10 = (acc1[nt][2] > 0.1f && gr0 + 8 != jg)     ? __expf(f0 - mrow1) : 0.f;
            float w11 = (acc1[nt][3] > 0.1f && gr0 + 8 != jg + 1) ? __expf(f1 - mrow1) : 0.f;
            __nv_bfloat16 b00 = __float2bfloat16(w00), b01 = __float2bfloat16(w01);
            __nv_bfloat16 b10 = __float2bfloat16(w10), b11 = __float2bfloat16(w11);
            den0 += __bfloat162float(b00) + __bfloat162float(b01);
            den1 += __bfloat162float(b10) + __bfloat162float(b11);
            unsigned p0 = ((unsigned)__bfloat16_as_ushort(b01) << 16) | __bfloat16_as_ushort(b00);
            unsigned p1 = ((unsigned)__bfloat16_as_ushort(b11) << 16) | __bfloat16_as_ushort(b10);
            int r0l = mt * 16 + crow;
            *(unsigned*)(sm + SA_W + r0l * 144 + jl * 2) = p0;
            *(unsigned*)(sm + SA_W + (r0l + 8) * 144 + jl * 2) = p1;
        }
        __syncthreads();

        // phase 2: NUM += W[64x64] @ HST[64x128]^T-form
        #pragma unroll
        for (int k = 0; k < 4; k++) {
            unsigned a0, a1, a2, a3;
            ldsm4(sb + SA_W + (unsigned)rowA * 144 + colA + k * 32, a0, a1, a2, a3);
            #pragma unroll
            for (int ntp = 0; ntp < 4; ntp++) {
                unsigned b0, b1, b2, b3;
                ldsm4(sb + SA_HST + (unsigned)(nh * 64 + ntp * 16 + rowBl) * 144 + colB + k * 32,
                      b0, b1, b2, b3);
                mma_bf16(acc2[ntp * 2],     a0, a1, a2, a3, b0, b1);
                mma_bf16(acc2[ntp * 2 + 1], a0, a1, a2, a3, b2, b3);
            }
        }
    }

    if (curType >= 0) {
        int gr0 = r0g + mt * 16 + crow;
        #pragma unroll
        for (int nt = 0; nt < 8; nt++) {
            int d = nh * 64 + nt * 8 + ccol;
            float* b0 = acc + ((size_t)curType * NA + gr0) * 128 + d;
            float* b1 = acc + ((size_t)curType * NA + gr0 + 8) * 128 + d;
            atomicAdd(b0, acc2[nt][0]); atomicAdd(b0 + 1, acc2[nt][1]);
            atomicAdd(b1, acc2[nt][2]); atomicAdd(b1 + 1, acc2[nt][3]);
        }
        float d0 = den0 + __shfl_xor_sync(0xffffffffu, den0, 1);
        d0 += __shfl_xor_sync(0xffffffffu, d0, 2);
        float d1 = den1 + __shfl_xor_sync(0xffffffffu, den1, 1);
        d1 += __shfl_xor_sync(0xffffffffu, d1, 2);
        if ((lane & 3) == 0) {
            atomicAdd(deng + curType * NA + gr0, d0);
            atomicAdd(deng + curType * NA + gr0 + 8, d1);
        }
    }
}

__global__ void finalize_kernel(float* __restrict__ acc, const float* __restrict__ den,
                                const float* __restrict__ gb) {
    int idx = blockIdx.x * blockDim.x + threadIdx.x;
    if (idx >= 3 * NA * 128) return;
    int c = idx & 127, dr = idx >> 7, type = idx >> 19;
    float d = den[dr], b = gb[type * 128 + c];
    acc[idx] = (d > 0.f) ? acc[idx] / d + b : b;
}

__global__ void attscore_kernel(const float* __restrict__ heter, const float* __restrict__ xt,
                                const float* __restrict__ Watt, const float* __restrict__ atts,
                                float* __restrict__ ssum) {
    int set = blockIdx.y;
    const float* X = (set < 3) ? heter + (size_t)set * NA * 128 : xt;
    int rb = blockIdx.x * 4, t = threadIdx.x, c = t & 63;
    __shared__ float xs[4][128];
    for (int i = t; i < 512; i += 256)
        xs[i >> 7][i & 127] = X[(size_t)(rb + (i >> 7)) * 128 + (i & 127)];
    __syncthreads();
    const float* xr = xs[t >> 6];
    float dot = 0.f;
    #pragma unroll 8
    for (int k = 0; k < 128; k++) dot += xr[k] * Watt[k * 64 + c];
    float val = (1.f / (1.f + __expf(-dot))) * atts[set * 64 + c];
    #pragma unroll
    for (int o = 16; o; o >>= 1) val += __shfl_xor_sync(0xffffffffu, val, o);
    __shared__ float ps[8];
    if ((t & 31) == 0) ps[t >> 5] = val;
    __syncthreads();
    if (t == 0) {
        float s = 0.f;
        #pragma unroll
        for (int i = 0; i < 8; i++) s += ps[i];
        atomicAdd(&ssum[set], s);
    }
}

__global__ void alpha_kernel(const float* __restrict__ ssum, float* __restrict__ alpha) {
    if (threadIdx.x == 0) {
        float s[4], m = -3e38f;
        for (int i = 0; i < 4; i++) { s[i] = ssum[i] / (float)NA; m = fmaxf(m, s[i]); }
        float e[4], tot = 0.f;
        for (int i = 0; i < 4; i++) { e[i] = expf(s[i] - m); tot += e[i]; }
        for (int i = 0; i < 4; i++) alpha[i] = e[i] / tot;
    }
}

__global__ void xatt_kernel(const float* __restrict__ heter, const float* __restrict__ xt,
                            const float* __restrict__ alpha, float* __restrict__ out) {
    int idx = blockIdx.x * blockDim.x + threadIdx.x;
    if (idx >= NA * 128) return;
    out[idx] = alpha[0] * heter[idx] + alpha[1] * heter[NA * 128 + idx] +
               alpha[2] * heter[2 * NA * 128 + idx] + alpha[3] * xt[idx];
}

__global__ void deg_kernel(const int* __restrict__ dst, float* __restrict__ deg, int E) {
    int e = blockIdx.x * blockDim.x + threadIdx.x;
    if (e < E) atomicAdd(&deg[dst[e]], 1.0f);
}

__global__ void scatter_kernel(const float* __restrict__ X, const int* __restrict__ src,
                               const int* __restrict__ dst, float* __restrict__ AGG,
                               int E, int C) {
    int idx = blockIdx.x * blockDim.x + threadIdx.x;
    int per = C >> 2;
    if (idx >= E * per) return;
    int e = idx / per, q = idx - e * per;
    int s = src[e], d = dst[e];
    float4 v = *(const float4*)&X[(size_t)s * C + q * 4];
    float* o = &AGG[(size_t)d * C + q * 4];
    atomicAdd(o + 0, v.x); atomicAdd(o + 1, v.y);
    atomicAdd(o + 2, v.z); atomicAdd(o + 3, v.w);
}

__global__ void rowdiv_kernel(float* __restrict__ AGG, const float* __restrict__ deg,
                              int n, int C) {
    int idx = blockIdx.x * blockDim.x + threadIdx.x;
    if (idx >= n) return;
    AGG[idx] = AGG[idx] / fmaxf(deg[idx / C], 1.0f);
}

extern "C" void kernel_launch(void* const* d_in, const int* in_sizes, int n_in,
                              void* d_out, int out_size) {
    const float* x_ma = (const float*)d_in[0];
    const float* x_mp = (const float*)d_in[1];
    const float* x_mt = (const float*)d_in[2];
    const float* x_mc = (const float*)d_in[3];
    const float* x_ia = (const float*)d_in[4];
    const int*   edge = (const int*)d_in[5];
    const float* Wla  = (const float*)d_in[6];  const float* bla  = (const float*)d_in[7];
    const float* Wlp  = (const float*)d_in[8];  const float* blp  = (const float*)d_in[9];
    const float* Wlt  = (const float*)d_in[10]; const float* blt  = (const float*)d_in[11];
    const float* Wlc  = (const float*)d_in[12]; const float* blc  = (const float*)d_in[13];
    const float* Wltg = (const float*)d_in[14]; const float* bltg = (const float*)d_in[15];
    const float* gWs  = (const float*)d_in[16];
    const float* gWd  = (const float*)d_in[17];
    const float* gas  = (const float*)d_in[18];
    const float* gad  = (const float*)d_in[19];
    const float* gb   = (const float*)d_in[20];
    const float* Watt = (const float*)d_in[21];
    const float* atts = (const float*)d_in[22];
    const float* W1l  = (const float*)d_in[23]; const float* b1 = (const float*)d_in[24];
    const float* W1r  = (const float*)d_in[25];
    const float* W2l  = (const float*)d_in[26]; const float* b2 = (const float*)d_in[27];
    const float* W2r  = (const float*)d_in[28];

    int E = in_sizes[5] / 2;
    int Ka = in_sizes[0] / NA, Kp = in_sizes[1] / NP, Kt = in_sizes[2] / NT;
    int Kc = in_sizes[3] / NC, Kg = in_sizes[4] / NA;

    float* out_x   = (float*)d_out;
    float* out_att = (float*)d_out + (size_t)NA * 64;

    float *ha,*hp,*ht,*hc,*xt,*gp,*gt,*gc;
    float *alsp,*alst,*alsc,*ald,*wdv,*acc,*den,*ssum,*alpha,*agg1,*deg,*h1,*q,*aggq;
    unsigned* mxsEnc;
    __nv_bfloat16 *anh,*anl,*snh,*snl,*hsT;
    cudaGetSymbolAddress((void**)&ha,g_ha);   cudaGetSymbolAddress((void**)&hp,g_hp);
    cudaGetSymbolAddress((void**)&ht,g_ht);   cudaGetSymbolAddress((void**)&hc,g_hc);
    cudaGetSymbolAddress((void**)&xt,g_xt);
    cudaGetSymbolAddress((void**)&anh,g_anh); cudaGetSymbolAddress((void**)&anl,g_anl);
    cudaGetSymbolAddress((void**)&snh,g_snh); cudaGetSymbolAddress((void**)&snl,g_snl);
    cudaGetSymbolAddress((void**)&hsT,g_hsT); cudaGetSymbolAddress((void**)&gp,g_gp);
    cudaGetSymbolAddress((void**)&gt,g_gt);   cudaGetSymbolAddress((void**)&gc,g_gc);
    cudaGetSymbolAddress((void**)&alsp,g_alsp); cudaGetSymbolAddress((void**)&alst,g_alst);
    cudaGetSymbolAddress((void**)&alsc,g_alsc); cudaGetSymbolAddress((void**)&ald,g_ald);
    cudaGetSymbolAddress((void**)&wdv,g_wdv);   cudaGetSymbolAddress((void**)&mxsEnc,g_mxsEnc);
    cudaGetSymbolAddress((void**)&acc,g_acc);   cudaGetSymbolAddress((void**)&den,g_den);
    cudaGetSymbolAddress((void**)&ssum,g_ssum); cudaGetSymbolAddress((void**)&alpha,g_alpha);
    cudaGetSymbolAddress((void**)&agg1,g_agg1); cudaGetSymbolAddress((void**)&deg,g_deg);
    cudaGetSymbolAddress((void**)&h1,g_h1);     cudaGetSymbolAddress((void**)&q,g_q);
    cudaGetSymbolAddress((void**)&aggq,g_aggq);

    auto mkjob = [](const float*A,const float*W,const float*A2,const float*W2,
                    const float*bias,const float*addD,const float*degp,float*C,
                    int M,int K,int K2,int N,int relu,int colBlks,int blkStart){
        LJob J; J.A=A;J.W=W;J.A2=A2;J.W2=W2;J.bias=bias;J.addD=addD;J.degp=degp;J.C=C;
        J.M=M;J.K=K;J.K2=K2;J.N=N;J.relu=relu;J.colBlks=colBlks;J.blkStart=blkStart;
        return J;
    };

    wvec_kernel<<<3,128>>>(gWd, gad, wdv);
    zero_all<<<9281,256>>>(acc, agg1, aggq, den, deg, ssum, mxsEnc);
    {
        LJobs B; B.n = 5;
        B.j[0] = mkjob(x_ma, Wla,  0,0, bla,  0,0, ha, NA, Ka, 0, 128, 0, 1, 0);
        B.j[1] = mkjob(x_mp, Wlp,  0,0, blp,  0,0, hp, NP, Kp, 0, 128, 0, 1, 64);
        B.j[2] = mkjob(x_mt, Wlt,  0,0, blt,  0,0, ht, NT, Kt, 0, 128, 0, 1, 192);
        B.j[3] = mkjob(x_mc, Wlc,  0,0, blc,  0,0, hc, NC, Kc, 0, 128, 0, 1, 256);
        B.j[4] = mkjob(x_ia, Wltg, 0,0, bltg, 0,0, xt, NA, Kg, 0, 128, 0, 1, 288);
        lin_batch<<<352,256>>>(B);
    }
    {
        LJobs B; B.n = 3;
        B.j[0] = mkjob(hp, gWs + 0*16384, 0,0, 0,0,0, gp, NP, 128, 0, 128, 0, 1, 0);
        B.j[1] = mkjob(ht, gWs + 1*16384, 0,0, 0,0,0, gt, NT, 128, 0, 128, 0, 1, 128);
        B.j[2] = mkjob(hc, gWs + 2*16384, 0,0, 0,0,0, gc, NC, 128, 0, 128, 0, 1, 192);
        lin_batch<<<224,256>>>(B);
    }
    prep_all<<<46848,128>>>(ha, hp, ht, hc, anh, anl, snh, snl,
                            gp, gt, gc, wdv, gas, ald, alsp, alst, alsc, mxsEnc, hsT);
    cudaFuncSetAttribute(hetero_mma, cudaFuncAttributeMaxDynamicSharedMemorySize, SA_TOT);
    hetero_mma<<<HET_GRID,256,SA_TOT>>>(anh, anl, ald, mxsEnc, snh, snl, hsT,
                                        alsp, alst, alsc, acc, den);
    finalize_kernel<<<(3*NA*128)/256,256>>>(acc, den, gb);
    attscore_kernel<<<dim3(NA/4,4),256>>>(acc, xt, Watt, atts, ssum);
    alpha_kernel<<<1,32>>>(ssum, alpha);
    xatt_kernel<<<(NA*128)/256,256>>>(acc, xt, alpha, out_att);
    deg_kernel<<<(E+255)/256,256>>>(edge + E, deg, E);
    scatter_kernel<<<(E*32)/256,256>>>(ha, edge, edge + E, agg1, E, 128);
    rowdiv_kernel<<<(NA*128)/256,256>>>(agg1, deg, NA*128, 128);
    {
        LJobs B; B.n = 1;
        B.j[0] = mkjob(agg1, W1l, ha, W1r, b1, 0,0, h1, NA, 128, 128, 256, 1, 2, 0);
        lin_batch<<<128,256>>>(B);
    }
    {
        LJobs B; B.n = 1;
        B.j[0] = mkjob(h1, W2l, 0,0, 0,0,0, q, NA, 256, 0, 64, 0, 1, 0);
        lin_batch<<<64,256>>>(B);
    }
    scatter_kernel<<<(E*16)/256,256>>>(q, edge, edge + E, aggq, E, 64);
    {
        LJobs B; B.n = 1;
        B.j[0] = mkjob(h1, W2r, 0,0, b2, aggq, deg, out_x, NA, 256, 0, 64, 0, 1, 0);
        lin_batch<<<64,256>>>(B);
    }
}